// round 11
// baseline (speedup 1.0000x reference)
#include <cuda_runtime.h>
#include <cuda_fp16.h>
#include <cstdint>

#define NUM_CLASSES 100000
#define BATCH 512
#define EMBED 512

#define S_SCALE 64.0f
#define COS_M 0.8775825618903728f
#define SIN_M 0.479425538604203f
#define TH_V (-0.8775825618903728f)
#define MM_V 0.23971276930210156f

// scratch (no allocations allowed)
__device__ __half g_wh[(size_t)NUM_CLASSES * EMBED];  // fp16(w / ||w||)
__device__ __half g_xh[BATCH * EMBED];                // fp16(x)
__device__ float  g_rownll[BATCH];
__device__ int    g_label[BATCH];

// ---------------------------------------------------------------------------
// K0: label dtype autodetect (int64 vs int32) + materialize int32 labels.
// ---------------------------------------------------------------------------
__global__ void label_kernel(const int* __restrict__ raw) {
    __shared__ int s_or[16];
    int tid = threadIdx.x;
    int v = (tid & 1) ? raw[tid] : 0;
#pragma unroll
    for (int o = 16; o; o >>= 1) v |= __shfl_xor_sync(0xffffffffu, v, o);
    if ((tid & 31) == 0) s_or[tid >> 5] = v;
    __syncthreads();
    if (tid < 16) {
        int w = s_or[tid];
#pragma unroll
        for (int o = 8; o; o >>= 1) w |= __shfl_xor_sync(0xffffu, w, o);
        if (tid == 0) s_or[0] = w;
    }
    __syncthreads();
    bool is64 = (s_or[0] == 0);
    g_label[tid] = is64 ? raw[2 * tid] : raw[tid];
}

// ---------------------------------------------------------------------------
// K1a: W prep — normalize rows (fp32) + fp16 RNE convert. One warp per row.
// ---------------------------------------------------------------------------
__global__ void wprep_kernel(const float* __restrict__ w) {
    int gw   = (blockIdx.x * blockDim.x + threadIdx.x) >> 5;
    int lane = threadIdx.x & 31;
    if (gw >= NUM_CLASSES) return;
    const float4* row = (const float4*)(w + (size_t)gw * EMBED);
    float4 v[4];
    float s = 0.f;
#pragma unroll
    for (int i = 0; i < 4; i++) {
        v[i] = row[lane + i * 32];
        s += v[i].x * v[i].x + v[i].y * v[i].y + v[i].z * v[i].z + v[i].w * v[i].w;
    }
#pragma unroll
    for (int o = 16; o; o >>= 1) s += __shfl_xor_sync(0xffffffffu, s, o);
    float rn = 1.0f / fmaxf(__fsqrt_rn(s), 1e-12f);
    __half2* dst = (__half2*)(g_wh + (size_t)gw * EMBED);
#pragma unroll
    for (int i = 0; i < 4; i++) {
        int g2 = (lane + i * 32) * 2;
        dst[g2 + 0] = __floats2half2_rn(v[i].x * rn, v[i].y * rn);
        dst[g2 + 1] = __floats2half2_rn(v[i].z * rn, v[i].w * rn);
    }
}

// K1b: X prep — fp16 RNE convert.
__global__ void xprep_kernel(const float* __restrict__ x) {
    int i = blockIdx.x * 256 + threadIdx.x;   // over BATCH*EMBED/2
    float2 v = ((const float2*)x)[i];
    ((__half2*)g_xh)[i] = __floats2half2_rn(v.x, v.y);
}

// ---------------------------------------------------------------------------
// K2: fp16 GEMM (mma.sync m16n8k16, fp32 accum, ldmatrix) + ArcFace epilogue.
// CTA tile 64x128, 128 threads (4 warps, 1x4), warp tile 64x32.
// 4 CTAs/SM -> independent barrier domains overlap load/MMA phases.
// 3-stage cp.async pipeline, one __syncthreads per k-tile.
// smem rows padded to 40 halves (80B stride, ldmatrix conflict-free).
// ---------------------------------------------------------------------------
#define BM 64
#define BN 128
#define BK 32
#define ST 40               // halves per smem row (32 + 8 pad)
#define NKT (EMBED / BK)    // 16
#define A_H (BM * ST)       // 2560 halves
#define B_H (BN * ST)       // 5120 halves
#define STAGE_H (A_H + B_H) // 7680 halves
#define DSMEM_BYTES (3 * STAGE_H * 2)   // 46080 B

extern __shared__ __half dsm[];

__device__ __forceinline__ uint32_t smem_u32(const void* p) {
    return (uint32_t)__cvta_generic_to_shared(p);
}
__device__ __forceinline__ void cp_async16(void* smem, const void* gsrc, bool pred) {
    uint32_t sa = smem_u32(smem);
    int sz = pred ? 16 : 0;
    asm volatile("cp.async.cg.shared.global [%0], [%1], 16, %2;\n"
                 :: "r"(sa), "l"(gsrc), "r"(sz));
}
__device__ __forceinline__ void ldsm_x4(uint32_t& r0, uint32_t& r1,
                                        uint32_t& r2, uint32_t& r3, uint32_t addr) {
    asm volatile("ldmatrix.sync.aligned.m8n8.x4.shared.b16 {%0,%1,%2,%3}, [%4];"
                 : "=r"(r0), "=r"(r1), "=r"(r2), "=r"(r3) : "r"(addr));
}
__device__ __forceinline__ void mma_f16(float* d, const uint32_t* a, const uint32_t* b) {
    asm volatile(
        "mma.sync.aligned.m16n8k16.row.col.f32.f16.f16.f32 "
        "{%0,%1,%2,%3}, {%4,%5,%6,%7}, {%8,%9}, {%0,%1,%2,%3};\n"
        : "+f"(d[0]), "+f"(d[1]), "+f"(d[2]), "+f"(d[3])
        : "r"(a[0]), "r"(a[1]), "r"(a[2]), "r"(a[3]), "r"(b[0]), "r"(b[1]));
}
__device__ __forceinline__ float arcface_val(float c, bool is_label) {
    if (is_label) {
        float s2 = fminf(fmaxf(1.0f - c * c, 0.0f), 1.0f);
        float phi = c * COS_M - sqrtf(s2) * SIN_M;
        c = (c > TH_V) ? phi : (c - MM_V);
    }
    return c * S_SCALE;
}

__global__ void __launch_bounds__(128, 4)
arcface_gemm_f16(float* __restrict__ out) {
    const int m0 = blockIdx.x * BM;   // 8 batch tiles (fast dim -> W reuse in L2)
    const int n0 = blockIdx.y * BN;   // 782 class tiles
    const int tid  = threadIdx.x;
    const int wn   = tid >> 5, lane = tid & 31;   // 4 warps across N
    const int grp = lane >> 2, tig = lane & 3;

    float acc[4][4][4];
#pragma unroll
    for (int i = 0; i < 4; i++)
#pragma unroll
        for (int j = 0; j < 4; j++)
#pragma unroll
            for (int k = 0; k < 4; k++) acc[i][j][k] = 0.f;

    // ldmatrix per-lane byte offsets within a stage buffer
    const int g8 = lane >> 3, rw = lane & 7;
    // A x4: quads (m 0..7,k0)(m 8..15,k0)(m 0..7,k8)(m 8..15,k8); + mt*16 rows
    const uint32_t a_off = (uint32_t)((((g8 & 1) * 8 + rw) * ST + (g8 >> 1) * 8) * 2);
    // B x4 (pair p): (n=2p*8..,k0)(2p,k8)(2p+1,k0)(2p+1,k8)
    const uint32_t b_off0 = (uint32_t)(A_H * 2 +
                    (((wn * 32 + (g8 >> 1) * 8 + rw) * ST + (g8 & 1) * 8) * 2));
    const uint32_t b_off1 = b_off0 + 16 * ST * 2;

    // loader: A 256 chunks + B 512 chunks of 16B over 128 threads -> 6 each
    auto load_tiles = [&](int kt) {
        __half* stg = dsm + (kt % 3) * STAGE_H;
        const int r4 = tid >> 2;          // 0..31
        const int c8 = (tid & 3) * 8;     // half offset of 16B chunk
#pragma unroll
        for (int i = 0; i < 2; i++) {     // A rows: 32*i + r4
            int row = i * 32 + r4;
            cp_async16(stg + row * ST + c8,
                       g_xh + (size_t)(m0 + row) * EMBED + kt * BK + c8, true);
        }
#pragma unroll
        for (int i = 0; i < 4; i++) {     // B rows: 32*i + r4
            int row = i * 32 + r4;
            bool p = (n0 + row) < NUM_CLASSES;
            cp_async16(stg + A_H + row * ST + c8,
                       g_wh + (size_t)(n0 + row) * EMBED + kt * BK + c8, p);
        }
        asm volatile("cp.async.commit_group;\n");
    };

    load_tiles(0);
    load_tiles(1);

    for (int kt = 0; kt < NKT; kt++) {
        if (kt < NKT - 2) asm volatile("cp.async.wait_group 1;\n");
        else              asm volatile("cp.async.wait_group 0;\n");
        __syncthreads();   // data kt visible; compute kt-1 done by all warps

        if (kt + 2 < NKT) load_tiles(kt + 2);   // buf (kt+2)%3 == (kt-1)%3: free

        const uint32_t Sb = smem_u32(dsm + (kt % 3) * STAGE_H);
#pragma unroll
        for (int kk = 0; kk < BK / 16; kk++) {
            const uint32_t kb = kk * 32;   // 16 halves = 32 bytes
            uint32_t af[4][4], bf[4][2];
            ldsm_x4(bf[0][0], bf[0][1], bf[1][0], bf[1][1], Sb + b_off0 + kb);
            ldsm_x4(bf[2][0], bf[2][1], bf[3][0], bf[3][1], Sb + b_off1 + kb);
#pragma unroll
            for (int mt = 0; mt < 4; mt++)
                ldsm_x4(af[mt][0], af[mt][1], af[mt][2], af[mt][3],
                        Sb + a_off + mt * (16 * ST * 2) + kb);
#pragma unroll
            for (int mt = 0; mt < 4; mt++)
#pragma unroll
                for (int nt = 0; nt < 4; nt++)
                    mma_f16(acc[mt][nt], af[mt], bf[nt]);
        }
    }

    // Epilogue: ArcFace margin at label column, * S.
#pragma unroll
    for (int mt = 0; mt < 4; mt++) {
        int m_lo = m0 + mt * 16 + grp;
        int m_hi = m_lo + 8;
        int lbl_lo = g_label[m_lo];
        int lbl_hi = g_label[m_hi];
#pragma unroll
        for (int nt = 0; nt < 4; nt++) {
            int n = n0 + wn * 32 + nt * 8 + 2 * tig;
            float* a = acc[mt][nt];
            if (n < NUM_CLASSES) {
                out[(size_t)m_lo * NUM_CLASSES + n] = arcface_val(a[0], n == lbl_lo);
                out[(size_t)m_hi * NUM_CLASSES + n] = arcface_val(a[2], n == lbl_hi);
            }
            if (n + 1 < NUM_CLASSES) {
                out[(size_t)m_lo * NUM_CLASSES + n + 1] = arcface_val(a[1], (n + 1) == lbl_lo);
                out[(size_t)m_hi * NUM_CLASSES + n + 1] = arcface_val(a[3], (n + 1) == lbl_hi);
            }
        }
    }
}

// ---------------------------------------------------------------------------
// K3: per-row online logsumexp over 100000 logits -> per-row NLL.
// ---------------------------------------------------------------------------
__global__ void lse_kernel(const float* __restrict__ logits) {
    const int row = blockIdx.x;
    const int tid = threadIdx.x;
    const float4* p = (const float4*)(logits + (size_t)row * NUM_CLASSES);
    const int n4 = NUM_CLASSES / 4;

    float m = -INFINITY, s = 0.f;
    for (int i = tid; i < n4; i += 512) {
        float4 v = p[i];
        float mx = fmaxf(fmaxf(v.x, v.y), fmaxf(v.z, v.w));
        if (mx > m) { s *= __expf(m - mx); m = mx; }
        s += __expf(v.x - m) + __expf(v.y - m) + __expf(v.z - m) + __expf(v.w - m);
    }

    __shared__ float sm[512];
    __shared__ float ss[512];
    sm[tid] = m; ss[tid] = s;
    __syncthreads();
    for (int o = 256; o; o >>= 1) {
        if (tid < o) {
            float m1 = sm[tid], s1 = ss[tid];
            float m2 = sm[tid + o], s2 = ss[tid + o];
            float mm = fmaxf(m1, m2);
            sm[tid] = mm;
            ss[tid] = s1 * __expf(m1 - mm) + s2 * __expf(m2 - mm);
        }
        __syncthreads();
    }
    if (tid == 0) {
        float logZ = sm[0] + __logf(ss[0]);
        int lbl = g_label[row];
        g_rownll[row] = logZ - logits[(size_t)row * NUM_CLASSES + lbl];
    }
}

// ---------------------------------------------------------------------------
// K4: loss = mean(rownll).
// ---------------------------------------------------------------------------
__global__ void loss_kernel(float* __restrict__ out, int out_size) {
    __shared__ float sm[BATCH];
    sm[threadIdx.x] = g_rownll[threadIdx.x];
    __syncthreads();
    for (int o = 256; o; o >>= 1) {
        if (threadIdx.x < o) sm[threadIdx.x] += sm[threadIdx.x + o];
        __syncthreads();
    }
    if (threadIdx.x == 0) {
        long long total = (long long)BATCH * NUM_CLASSES;
        if ((long long)out_size > total)
            out[total] = sm[0] * (1.0f / BATCH);
    }
}

// ---------------------------------------------------------------------------
extern "C" void kernel_launch(void* const* d_in, const int* in_sizes, int n_in,
                              void* d_out, int out_size) {
    const float* X        = (const float*)d_in[0];
    const int*   labelRaw = (const int*)d_in[1];
    const float* W        = (const float*)d_in[2];
    float* out = (float*)d_out;

    static bool attr_done = false;
    if (!attr_done) {
        cudaFuncSetAttribute(arcface_gemm_f16,
                             cudaFuncAttributeMaxDynamicSharedMemorySize, DSMEM_BYTES);
        attr_done = true;
    }

    label_kernel<<<1, BATCH>>>(labelRaw);
    xprep_kernel<<<BATCH * EMBED / 512, 256>>>(X);
    wprep_kernel<<<NUM_CLASSES / 8, 256>>>(W);

    dim3 grid(BATCH / BM, (NUM_CLASSES + BN - 1) / BN);  // (8, 782)
    arcface_gemm_f16<<<grid, 128, DSMEM_BYTES>>>(out);

    lse_kernel<<<BATCH, 512>>>(out);
    loss_kernel<<<1, BATCH>>>(out, out_size);
}

// round 12
// speedup vs baseline: 1.0380x; 1.0380x over previous
#include <cuda_runtime.h>
#include <cuda_fp16.h>
#include <cstdint>

#define NUM_CLASSES 100000
#define BATCH 512
#define EMBED 512

#define S_SCALE 64.0f
#define COS_M 0.8775825618903728f
#define SIN_M 0.479425538604203f
#define TH_V (-0.8775825618903728f)
#define MM_V 0.23971276930210156f

// scratch (no allocations allowed)
__device__ __half g_wh[(size_t)NUM_CLASSES * EMBED];  // fp16(w / ||w||)
__device__ __half g_xh[BATCH * EMBED];                // fp16(x)
__device__ float  g_rownll[BATCH];
__device__ int    g_label[BATCH];

// ---------------------------------------------------------------------------
// K0: label dtype autodetect (int64 vs int32) + materialize int32 labels.
// ---------------------------------------------------------------------------
__global__ void label_kernel(const int* __restrict__ raw) {
    __shared__ int s_or[16];
    int tid = threadIdx.x;
    int v = (tid & 1) ? raw[tid] : 0;
#pragma unroll
    for (int o = 16; o; o >>= 1) v |= __shfl_xor_sync(0xffffffffu, v, o);
    if ((tid & 31) == 0) s_or[tid >> 5] = v;
    __syncthreads();
    if (tid < 16) {
        int w = s_or[tid];
#pragma unroll
        for (int o = 8; o; o >>= 1) w |= __shfl_xor_sync(0xffffu, w, o);
        if (tid == 0) s_or[0] = w;
    }
    __syncthreads();
    bool is64 = (s_or[0] == 0);
    g_label[tid] = is64 ? raw[2 * tid] : raw[tid];
}

// ---------------------------------------------------------------------------
// K1a: W prep — normalize rows (fp32) + fp16 RNE convert. One warp per row.
// ---------------------------------------------------------------------------
__global__ void wprep_kernel(const float* __restrict__ w) {
    int gw   = (blockIdx.x * blockDim.x + threadIdx.x) >> 5;
    int lane = threadIdx.x & 31;
    if (gw >= NUM_CLASSES) return;
    const float4* row = (const float4*)(w + (size_t)gw * EMBED);
    float4 v[4];
    float s = 0.f;
#pragma unroll
    for (int i = 0; i < 4; i++) {
        v[i] = row[lane + i * 32];
        s += v[i].x * v[i].x + v[i].y * v[i].y + v[i].z * v[i].z + v[i].w * v[i].w;
    }
#pragma unroll
    for (int o = 16; o; o >>= 1) s += __shfl_xor_sync(0xffffffffu, s, o);
    float rn = 1.0f / fmaxf(__fsqrt_rn(s), 1e-12f);
    __half2* dst = (__half2*)(g_wh + (size_t)gw * EMBED);
#pragma unroll
    for (int i = 0; i < 4; i++) {
        int g2 = (lane + i * 32) * 2;
        dst[g2 + 0] = __floats2half2_rn(v[i].x * rn, v[i].y * rn);
        dst[g2 + 1] = __floats2half2_rn(v[i].z * rn, v[i].w * rn);
    }
}

// K1b: X prep — fp16 RNE convert.
__global__ void xprep_kernel(const float* __restrict__ x) {
    int i = blockIdx.x * 256 + threadIdx.x;   // over BATCH*EMBED/2
    float2 v = ((const float2*)x)[i];
    ((__half2*)g_xh)[i] = __floats2half2_rn(v.x, v.y);
}

// ---------------------------------------------------------------------------
// K2: fp16 GEMM (mma.sync m16n8k16, fp32 accum, ldmatrix) + ArcFace epilogue.
// CTA tile 64x128, 128 threads (4 warps), warp tile 64x32. BK=64 (4 kk-steps),
// 2-stage cp.async pipeline, INTRA-WARP fragment double-buffering: ldmatrix
// for kk+1 issues before the MMAs of kk -> no stall-burst phase coherence.
// smem rows 72 halves (144B stride): ldmatrix 8-row quads on distinct banks.
// ---------------------------------------------------------------------------
#define BM 64
#define BN 128
#define BK 64
#define ST 72                // halves per smem row (64 + 8 pad), 144B stride
#define NKT (EMBED / BK)     // 8
#define A_H (BM * ST)        // 4608 halves
#define B_H (BN * ST)        // 9216 halves
#define STAGE_H (A_H + B_H)  // 13824 halves
#define DSMEM_BYTES (2 * STAGE_H * 2)   // 55296 B

extern __shared__ __half dsm[];

__device__ __forceinline__ uint32_t smem_u32(const void* p) {
    return (uint32_t)__cvta_generic_to_shared(p);
}
__device__ __forceinline__ void cp_async16(void* smem, const void* gsrc, bool pred) {
    uint32_t sa = smem_u32(smem);
    int sz = pred ? 16 : 0;
    asm volatile("cp.async.cg.shared.global [%0], [%1], 16, %2;\n"
                 :: "r"(sa), "l"(gsrc), "r"(sz));
}
__device__ __forceinline__ void ldsm_x4(uint32_t& r0, uint32_t& r1,
                                        uint32_t& r2, uint32_t& r3, uint32_t addr) {
    asm volatile("ldmatrix.sync.aligned.m8n8.x4.shared.b16 {%0,%1,%2,%3}, [%4];"
                 : "=r"(r0), "=r"(r1), "=r"(r2), "=r"(r3) : "r"(addr));
}
__device__ __forceinline__ void mma_f16(float* d, const uint32_t* a, const uint32_t* b) {
    asm volatile(
        "mma.sync.aligned.m16n8k16.row.col.f32.f16.f16.f32 "
        "{%0,%1,%2,%3}, {%4,%5,%6,%7}, {%8,%9}, {%0,%1,%2,%3};\n"
        : "+f"(d[0]), "+f"(d[1]), "+f"(d[2]), "+f"(d[3])
        : "r"(a[0]), "r"(a[1]), "r"(a[2]), "r"(a[3]), "r"(b[0]), "r"(b[1]));
}
__device__ __forceinline__ float arcface_val(float c, bool is_label) {
    if (is_label) {
        float s2 = fminf(fmaxf(1.0f - c * c, 0.0f), 1.0f);
        float phi = c * COS_M - sqrtf(s2) * SIN_M;
        c = (c > TH_V) ? phi : (c - MM_V);
    }
    return c * S_SCALE;
}

__global__ void __launch_bounds__(128, 3)
arcface_gemm_f16(float* __restrict__ out) {
    const int m0 = blockIdx.x * BM;   // 8 batch tiles (fast dim -> W reuse in L2)
    const int n0 = blockIdx.y * BN;   // 782 class tiles
    const int tid  = threadIdx.x;
    const int wn   = tid >> 5, lane = tid & 31;   // 4 warps across N
    const int grp = lane >> 2, tig = lane & 3;

    float acc[4][4][4];
#pragma unroll
    for (int i = 0; i < 4; i++)
#pragma unroll
        for (int j = 0; j < 4; j++)
#pragma unroll
            for (int k = 0; k < 4; k++) acc[i][j][k] = 0.f;

    // ldmatrix per-lane byte offsets within a stage buffer
    const int g8 = lane >> 3, rw = lane & 7;
    const uint32_t a_off = (uint32_t)((((g8 & 1) * 8 + rw) * ST + (g8 >> 1) * 8) * 2);
    const uint32_t b_off0 = (uint32_t)(A_H * 2 +
                    (((wn * 32 + (g8 >> 1) * 8 + rw) * ST + (g8 & 1) * 8) * 2));
    const uint32_t b_off1 = b_off0 + 16 * ST * 2;

    // loader: A 512 + B 1024 chunks of 16B over 128 threads -> 12 each
    auto load_tiles = [&](int kt) {
        __half* stg = dsm + (kt & 1) * STAGE_H;
#pragma unroll
        for (int i = 0; i < 4; i++) {      // A: 64 rows x 8 chunks
            int id  = tid + i * 128;
            int row = id >> 3, c8 = (id & 7) * 8;
            cp_async16(stg + row * ST + c8,
                       g_xh + (size_t)(m0 + row) * EMBED + kt * BK + c8, true);
        }
#pragma unroll
        for (int i = 0; i < 8; i++) {      // B: 128 rows x 8 chunks
            int id  = tid + i * 128;
            int row = id >> 3, c8 = (id & 7) * 8;
            bool p = (n0 + row) < NUM_CLASSES;
            cp_async16(stg + A_H + row * ST + c8,
                       g_wh + (size_t)(n0 + row) * EMBED + kt * BK + c8, p);
        }
        asm volatile("cp.async.commit_group;\n");
    };

    uint32_t af[2][4][4], bf[2][4][2];

    auto frag_load = [&](uint32_t Sb, int kk, int slot) {
        const uint32_t kb = kk * 32;   // 16 halves = 32 bytes
        ldsm_x4(bf[slot][0][0], bf[slot][0][1], bf[slot][1][0], bf[slot][1][1],
                Sb + b_off0 + kb);
        ldsm_x4(bf[slot][2][0], bf[slot][2][1], bf[slot][3][0], bf[slot][3][1],
                Sb + b_off1 + kb);
#pragma unroll
        for (int mt = 0; mt < 4; mt++)
            ldsm_x4(af[slot][mt][0], af[slot][mt][1], af[slot][mt][2], af[slot][mt][3],
                    Sb + a_off + mt * (16 * ST * 2) + kb);
    };

    load_tiles(0);
    load_tiles(1);

    for (int kt = 0; kt < NKT; kt++) {
        if (kt < NKT - 1) asm volatile("cp.async.wait_group 1;\n");
        else              asm volatile("cp.async.wait_group 0;\n");
        __syncthreads();   // tile kt visible to all warps

        const uint32_t Sb = smem_u32(dsm + (kt & 1) * STAGE_H);
        frag_load(Sb, 0, 0);
#pragma unroll
        for (int kk = 0; kk < BK / 16; kk++) {
            const int cur = kk & 1, nxt = cur ^ 1;
            if (kk + 1 < BK / 16) frag_load(Sb, kk + 1, nxt);  // overlap w/ MMAs
#pragma unroll
            for (int mt = 0; mt < 4; mt++)
#pragma unroll
                for (int nt = 0; nt < 4; nt++)
                    mma_f16(acc[mt][nt], af[cur][mt], bf[cur][nt]);
        }
        __syncthreads();   // all reads of buf kt&1 done before overwrite
        if (kt + 2 < NKT) load_tiles(kt + 2);
    }

    // Epilogue: ArcFace margin at label column, * S.
#pragma unroll
    for (int mt = 0; mt < 4; mt++) {
        int m_lo = m0 + mt * 16 + grp;
        int m_hi = m_lo + 8;
        int lbl_lo = g_label[m_lo];
        int lbl_hi = g_label[m_hi];
#pragma unroll
        for (int nt = 0; nt < 4; nt++) {
            int n = n0 + wn * 32 + nt * 8 + 2 * tig;
            float* a = acc[mt][nt];
            if (n < NUM_CLASSES) {
                out[(size_t)m_lo * NUM_CLASSES + n] = arcface_val(a[0], n == lbl_lo);
                out[(size_t)m_hi * NUM_CLASSES + n] = arcface_val(a[2], n == lbl_hi);
            }
            if (n + 1 < NUM_CLASSES) {
                out[(size_t)m_lo * NUM_CLASSES + n + 1] = arcface_val(a[1], (n + 1) == lbl_lo);
                out[(size_t)m_hi * NUM_CLASSES + n + 1] = arcface_val(a[3], (n + 1) == lbl_hi);
            }
        }
    }
}

// ---------------------------------------------------------------------------
// K3: per-row online logsumexp over 100000 logits -> per-row NLL.
// ---------------------------------------------------------------------------
__global__ void lse_kernel(const float* __restrict__ logits) {
    const int row = blockIdx.x;
    const int tid = threadIdx.x;
    const float4* p = (const float4*)(logits + (size_t)row * NUM_CLASSES);
    const int n4 = NUM_CLASSES / 4;

    float m = -INFINITY, s = 0.f;
    for (int i = tid; i < n4; i += 512) {
        float4 v = p[i];
        float mx = fmaxf(fmaxf(v.x, v.y), fmaxf(v.z, v.w));
        if (mx > m) { s *= __expf(m - mx); m = mx; }
        s += __expf(v.x - m) + __expf(v.y - m) + __expf(v.z - m) + __expf(v.w - m);
    }

    __shared__ float sm[512];
    __shared__ float ss[512];
    sm[tid] = m; ss[tid] = s;
    __syncthreads();
    for (int o = 256; o; o >>= 1) {
        if (tid < o) {
            float m1 = sm[tid], s1 = ss[tid];
            float m2 = sm[tid + o], s2 = ss[tid + o];
            float mm = fmaxf(m1, m2);
            sm[tid] = mm;
            ss[tid] = s1 * __expf(m1 - mm) + s2 * __expf(m2 - mm);
        }
        __syncthreads();
    }
    if (tid == 0) {
        float logZ = sm[0] + __logf(ss[0]);
        int lbl = g_label[row];
        g_rownll[row] = logZ - logits[(size_t)row * NUM_CLASSES + lbl];
    }
}

// ---------------------------------------------------------------------------
// K4: loss = mean(rownll).
// ---------------------------------------------------------------------------
__global__ void loss_kernel(float* __restrict__ out, int out_size) {
    __shared__ float sm[BATCH];
    sm[threadIdx.x] = g_rownll[threadIdx.x];
    __syncthreads();
    for (int o = 256; o; o >>= 1) {
        if (threadIdx.x < o) sm[threadIdx.x] += sm[threadIdx.x + o];
        __syncthreads();
    }
    if (threadIdx.x == 0) {
        long long total = (long long)BATCH * NUM_CLASSES;
        if ((long long)out_size > total)
            out[total] = sm[0] * (1.0f / BATCH);
    }
}

// ---------------------------------------------------------------------------
extern "C" void kernel_launch(void* const* d_in, const int* in_sizes, int n_in,
                              void* d_out, int out_size) {
    const float* X        = (const float*)d_in[0];
    const int*   labelRaw = (const int*)d_in[1];
    const float* W        = (const float*)d_in[2];
    float* out = (float*)d_out;

    static bool attr_done = false;
    if (!attr_done) {
        cudaFuncSetAttribute(arcface_gemm_f16,
                             cudaFuncAttributeMaxDynamicSharedMemorySize, DSMEM_BYTES);
        attr_done = true;
    }

    label_kernel<<<1, BATCH>>>(labelRaw);
    xprep_kernel<<<BATCH * EMBED / 512, 256>>>(X);
    wprep_kernel<<<NUM_CLASSES / 8, 256>>>(W);

    dim3 grid(BATCH / BM, (NUM_CLASSES + BN - 1) / BN);  // (8, 782)
    arcface_gemm_f16<<<grid, 128, DSMEM_BYTES>>>(out);

    lse_kernel<<<BATCH, 512>>>(out);
    loss_kernel<<<1, BATCH>>>(out, out_size);
}